// round 14
// baseline (speedup 1.0000x reference)
#include <cuda_runtime.h>
#include <cuda_bf16.h>

// Problem constants (from reference): B=16, V=4096, E=768
#define BB 16
#define VV 4096
#define EE 768
#define HALF_V (VV / 2)   // 2048

// out[b,v,e] = seq[b,v,0]*flux_w[v,e] + flux_b[v,e]
//            + seq[b,v,2]*time_w[v,e] + time_b[v,e]
//            + (e even ? sin : cos)( seq[b,v,1] * exp(-e_even*ln(10000)/E) )
//
// R13: per-thread ILP experiment. Each thread processes TWO v-rows
// (v, v+2048) at the same e, interleaved in one instruction stream:
//  - 8 independent weight LDG.128s batched at block start (2x MLP)
//  - 2 independent STG.128s per b-iter to 12MB-separated planes
//    (2x store-queue occupancy per warp)
//  - div_terms shared between the two rows (same e)
// Unlike R11's persistent loop (sequential v, lost MLP -> regressed),
// both rows live in the same iteration - nothing is serialized.
// All cache hints / TMA / occupancy levers previously measured neutral or
// negative; plain LDG.128/STG.128 retained.
__global__ __launch_bounds__(192) void bert_embed_kernel(
    const float* __restrict__ seq,   // [B, V, 3]
    const float* __restrict__ fw,    // [V, E]
    const float* __restrict__ fb,    // [V, E]
    const float* __restrict__ tw,    // [V, E]
    const float* __restrict__ tb,    // [V, E]
    float* __restrict__ out)         // [B, V, E]
{
    const int v0 = blockIdx.x;            // first row
    const int v1 = blockIdx.x + HALF_V;   // second row
    const int e  = threadIdx.x * 4;       // even-aligned
    const size_t base0 = (size_t)v0 * EE + e;
    const size_t base1 = (size_t)v1 * EE + e;

    // 8 independent weight loads issued up front (deep LDG batch).
    const float4 wf0 = *reinterpret_cast<const float4*>(fw + base0);
    const float4 wf1 = *reinterpret_cast<const float4*>(fw + base1);
    const float4 bf0 = *reinterpret_cast<const float4*>(fb + base0);
    const float4 bf1 = *reinterpret_cast<const float4*>(fb + base1);
    const float4 wt0 = *reinterpret_cast<const float4*>(tw + base0);
    const float4 wt1 = *reinterpret_cast<const float4*>(tw + base1);
    const float4 bt0 = *reinterpret_cast<const float4*>(tb + base0);
    const float4 bt1 = *reinterpret_cast<const float4*>(tb + base1);

    // Combined biases (saves 8 regs + FADDs in the loop).
    const float4 bs0 = make_float4(bf0.x + bt0.x, bf0.y + bt0.y,
                                   bf0.z + bt0.z, bf0.w + bt0.w);
    const float4 bs1 = make_float4(bf1.x + bt1.x, bf1.y + bt1.y,
                                   bf1.z + bt1.z, bf1.w + bt1.w);

    // div_term depends only on e — shared by both rows.
    const float c  = -9.210340371976184f / (float)EE;   // -ln(10000)/E
    const float d0 = __expf((float)e * c);
    const float d1 = __expf((float)(e + 2) * c);

    #pragma unroll
    for (int b = 0; b < BB; b++) {
        const float* s0p = seq + ((size_t)b * VV + v0) * 3;
        const float* s1p = seq + ((size_t)b * VV + v1) * 3;
        const float a0 = __ldg(s0p + 0), p0 = __ldg(s0p + 1), t0 = __ldg(s0p + 2);
        const float a1 = __ldg(s1p + 0), p1 = __ldg(s1p + 1), t1 = __ldg(s1p + 2);

        float sA0, cA0, sA1, cA1;   // row v0
        __sincosf(p0 * d0, &sA0, &cA0);
        __sincosf(p0 * d1, &sA1, &cA1);
        float sB0, cB0, sB1, cB1;   // row v1
        __sincosf(p1 * d0, &sB0, &cB0);
        __sincosf(p1 * d1, &sB1, &cB1);

        float4 o0, o1;
        o0.x = fmaf(a0, wf0.x, fmaf(t0, wt0.x, bs0.x)) + sA0;
        o0.y = fmaf(a0, wf0.y, fmaf(t0, wt0.y, bs0.y)) + cA0;
        o0.z = fmaf(a0, wf0.z, fmaf(t0, wt0.z, bs0.z)) + sA1;
        o0.w = fmaf(a0, wf0.w, fmaf(t0, wt0.w, bs0.w)) + cA1;
        o1.x = fmaf(a1, wf1.x, fmaf(t1, wt1.x, bs1.x)) + sB0;
        o1.y = fmaf(a1, wf1.y, fmaf(t1, wt1.y, bs1.y)) + cB0;
        o1.z = fmaf(a1, wf1.z, fmaf(t1, wt1.z, bs1.z)) + sB1;
        o1.w = fmaf(a1, wf1.w, fmaf(t1, wt1.w, bs1.w)) + cB1;

        // Two independent STG.128s, back-to-back (2x store-queue depth).
        const size_t plane = (size_t)b * (VV * EE);
        *reinterpret_cast<float4*>(out + plane + base0) = o0;
        *reinterpret_cast<float4*>(out + plane + base1) = o1;
    }
}

extern "C" void kernel_launch(void* const* d_in, const int* in_sizes, int n_in,
                              void* d_out, int out_size)
{
    const float* seq = (const float*)d_in[0];  // sequence [B,V,3]
    const float* fw  = (const float*)d_in[1];  // flux_w   [V,E]
    const float* fb  = (const float*)d_in[2];  // flux_b   [V,E]
    const float* tw  = (const float*)d_in[3];  // time_w   [V,E]
    const float* tb  = (const float*)d_in[4];  // time_b   [V,E]
    float* out = (float*)d_out;                // [B,V,E]

    dim3 grid(HALF_V);   // 2048 blocks, each covers v and v+2048
    dim3 block(EE / 4);  // 192 threads
    bert_embed_kernel<<<grid, block>>>(seq, fw, fb, tw, tb, out);
}

// round 15
// speedup vs baseline: 1.0315x; 1.0315x over previous
#include <cuda_runtime.h>
#include <cuda_bf16.h>

// Problem constants (from reference): B=16, V=4096, E=768
#define BB 16
#define VV 4096
#define EE 768

// out[b,v,e] = seq[b,v,0]*flux_w[v,e] + flux_b[v,e]
//            + seq[b,v,2]*time_w[v,e] + time_b[v,e]
//            + (e even ? sin : cos)( seq[b,v,1] * exp(-e_even*ln(10000)/E) )
//
// FINAL (= R3/R12, measured best: 43.07 & 43.49 us across two runs,
// ncu 37.1-37.7 us @ ~5.2 TB/s DRAM).
// One block per v (4096 blocks), 192 threads, thread owns 4 consecutive e.
// Weights loaded ONCE per (v,e) into registers; b-loop reuses them, so
// steady-state DRAM traffic is the compulsory 201 MB of output writes
// (weight tables are L2-resident across graph replays).
//
// Exhaustive search result — all measured neutral or negative vs this:
//   store path:  .cs (R4 -L1 throttle), evict_last (R7, worse), TMA 3KB
//                bulk store (R10, neutral: LTS cap is path-independent)
//   occupancy:   34%..82% (R8/R9/R10/R13) — DRAM pinned ~65% throughout
//   scheduling:  persistent grid (R11, lost cross-CTA MLP, regressed)
//   ILP:         2 v-rows/thread (R13, occupancy loss dominated)
// ~5.2 TB/s is the empirical write-only HBM ceiling on this part; the
// kernel is at its traffic floor.
__global__ __launch_bounds__(192) void bert_embed_kernel(
    const float* __restrict__ seq,   // [B, V, 3]
    const float* __restrict__ fw,    // [V, E]
    const float* __restrict__ fb,    // [V, E]
    const float* __restrict__ tw,    // [V, E]
    const float* __restrict__ tb,    // [V, E]
    float* __restrict__ out)         // [B, V, E]
{
    const int v = blockIdx.x;
    const int e = threadIdx.x * 4;           // even-aligned
    const size_t base = (size_t)v * EE + e;

    // Compulsory weight reads, kept in registers across the batch loop.
    const float4 wf = *reinterpret_cast<const float4*>(fw + base);
    const float4 bf = *reinterpret_cast<const float4*>(fb + base);
    const float4 wt = *reinterpret_cast<const float4*>(tw + base);
    const float4 bt = *reinterpret_cast<const float4*>(tb + base);

    // div_term for the two sin/cos pairs this thread owns.
    // div_term[i] = exp(2i * (-ln(10000)/E)); here 2i = e and e+2.
    const float c = -9.210340371976184f / (float)EE;   // -ln(10000)/E
    const float d0 = __expf((float)e * c);
    const float d1 = __expf((float)(e + 2) * c);

    #pragma unroll
    for (int b = 0; b < BB; b++) {
        const float* s = seq + ((size_t)b * VV + v) * 3;
        const float s0 = __ldg(s + 0);   // flux scalar (broadcast across block)
        const float s1 = __ldg(s + 1);   // passend
        const float s2 = __ldg(s + 2);   // time

        float sin0, cos0, sin1, cos1;
        __sincosf(s1 * d0, &sin0, &cos0);
        __sincosf(s1 * d1, &sin1, &cos1);

        float4 o;
        o.x = fmaf(s0, wf.x, bf.x) + fmaf(s2, wt.x, bt.x) + sin0;
        o.y = fmaf(s0, wf.y, bf.y) + fmaf(s2, wt.y, bt.y) + cos0;
        o.z = fmaf(s0, wf.z, bf.z) + fmaf(s2, wt.z, bt.z) + sin1;
        o.w = fmaf(s0, wf.w, bf.w) + fmaf(s2, wt.w, bt.w) + cos1;

        *reinterpret_cast<float4*>(out + (size_t)b * (VV * EE) + base) = o;
    }
}

extern "C" void kernel_launch(void* const* d_in, const int* in_sizes, int n_in,
                              void* d_out, int out_size)
{
    const float* seq = (const float*)d_in[0];  // sequence [B,V,3]
    const float* fw  = (const float*)d_in[1];  // flux_w   [V,E]
    const float* fb  = (const float*)d_in[2];  // flux_b   [V,E]
    const float* tw  = (const float*)d_in[3];  // time_w   [V,E]
    const float* tb  = (const float*)d_in[4];  // time_b   [V,E]
    float* out = (float*)d_out;                // [B,V,E]

    dim3 grid(VV);
    dim3 block(EE / 4);  // 192 threads
    bert_embed_kernel<<<grid, block>>>(seq, fw, fb, tw, tb, out);
}